// round 10
// baseline (speedup 1.0000x reference)
#include <cuda_runtime.h>
#include <cuda_bf16.h>
#include <cstdint>

#define B_    4
#define SQ_   2048
#define SK_   2048
#define D_    1024
#define H_    16
#define HD_   64
#define SCALE_ 0.125f
#define M_TOT (B_ * SQ_)   // 8192

// ---------------------------------------------------------------------------
// Scratch (__device__ globals per allocation rules)
// ---------------------------------------------------------------------------
__device__ __nv_bfloat16 g_qh[(size_t)M_TOT * D_], g_ql[(size_t)M_TOT * D_];
__device__ __nv_bfloat16 g_kh[(size_t)M_TOT * D_], g_kl[(size_t)M_TOT * D_];
__device__ __nv_bfloat16 g_ch[(size_t)M_TOT * D_], g_cl[(size_t)M_TOT * D_];

__device__ __nv_bfloat16 g_WqTh[D_ * D_],      g_WqTl[D_ * D_];
__device__ __nv_bfloat16 g_WkvTh[2 * D_ * D_], g_WkvTl[2 * D_ * D_];
__device__ __nv_bfloat16 g_WoTh[D_ * D_],      g_WoTl[D_ * D_];

// Per-head split arrays for attention: [b*H + h][seq][64]
__device__ __nv_bfloat16 g_Qh2[(size_t)M_TOT * D_], g_Ql2[(size_t)M_TOT * D_];
__device__ __nv_bfloat16 g_Kh2[(size_t)M_TOT * D_], g_Kl2[(size_t)M_TOT * D_];
__device__ __nv_bfloat16 g_Vh2[(size_t)M_TOT * D_], g_Vl2[(size_t)M_TOT * D_];

// ---------------------------------------------------------------------------
// Helpers
// ---------------------------------------------------------------------------
__device__ __forceinline__ uint32_t smem_u32(const void* p) {
    uint32_t a;
    asm("{ .reg .u64 t; cvta.to.shared.u64 t, %1; cvt.u32.u64 %0, t; }" : "=r"(a) : "l"(p));
    return a;
}

#define SW128(off) ((off) ^ (((off) >> 3) & 0x70))

#define CP16(dst, src) \
    asm volatile("cp.async.cg.shared.global [%0], [%1], 16;" \
                 :: "r"(dst), "l"(src) : "memory")
#define CP_COMMIT() asm volatile("cp.async.commit_group;" ::: "memory")
#define CP_WAIT1()  asm volatile("cp.async.wait_group 1;" ::: "memory")

#define LDSM_X4(r, addr) \
    asm volatile("ldmatrix.sync.aligned.m8n8.x4.shared.b16 {%0,%1,%2,%3}, [%4];" \
                 : "=r"((r)[0]), "=r"((r)[1]), "=r"((r)[2]), "=r"((r)[3]) : "r"(addr))
#define LDSM_X4_T(r, addr) \
    asm volatile("ldmatrix.sync.aligned.m8n8.x4.trans.shared.b16 {%0,%1,%2,%3}, [%4];" \
                 : "=r"((r)[0]), "=r"((r)[1]), "=r"((r)[2]), "=r"((r)[3]) : "r"(addr))

#define MMA16816(c, a, b) \
    asm volatile("mma.sync.aligned.m16n8k16.row.col.f32.bf16.bf16.f32 " \
                 "{%0,%1,%2,%3}, {%4,%5,%6,%7}, {%8,%9}, {%0,%1,%2,%3};" \
                 : "+f"((c)[0]), "+f"((c)[1]), "+f"((c)[2]), "+f"((c)[3]) \
                 : "r"((a)[0]), "r"((a)[1]), "r"((a)[2]), "r"((a)[3]), \
                   "r"((b)[0]), "r"((b)[1]))

__device__ __forceinline__ void split2(float x, float y, uint32_t& hi, uint32_t& lo) {
    __nv_bfloat162 h = __floats2bfloat162_rn(x, y);
    float hx = __bfloat162float(h.x), hy = __bfloat162float(h.y);
    __nv_bfloat162 l = __floats2bfloat162_rn(x - hx, y - hy);
    hi = reinterpret_cast<uint32_t&>(h);
    lo = reinterpret_cast<uint32_t&>(l);
}

// ---------------------------------------------------------------------------
// Prep kernels
// ---------------------------------------------------------------------------
__global__ void prep_act(const float* __restrict__ X,
                         __nv_bfloat16* __restrict__ Xh,
                         __nv_bfloat16* __restrict__ Xl, int n4) {
    int i = blockIdx.x * blockDim.x + threadIdx.x;
    int stride = gridDim.x * blockDim.x;
    for (; i < n4; i += stride) {
        float4 v = ((const float4*)X)[i];
        uint32_t h0, l0, h1, l1;
        split2(v.x, v.y, h0, l0);
        split2(v.z, v.w, h1, l1);
        ((uint32_t*)Xh)[i * 2 + 0] = h0;
        ((uint32_t*)Xh)[i * 2 + 1] = h1;
        ((uint32_t*)Xl)[i * 2 + 0] = l0;
        ((uint32_t*)Xl)[i * 2 + 1] = l1;
    }
}

__global__ void prep_wT(const float* __restrict__ W,
                        __nv_bfloat16* __restrict__ Th,
                        __nv_bfloat16* __restrict__ Tl, int Kd, int Nd) {
    __shared__ float t[32][33];
    int n  = blockIdx.x * 32 + threadIdx.x;
    int k0 = blockIdx.y * 32;
    for (int i = threadIdx.y; i < 32; i += 8)
        t[i][threadIdx.x] = W[(size_t)(k0 + i) * Nd + n];
    __syncthreads();
    int nn = blockIdx.x * 32;
    for (int i = threadIdx.y; i < 32; i += 8) {
        float v = t[threadIdx.x][i];
        __nv_bfloat16 h = __float2bfloat16_rn(v);
        Th[(size_t)(nn + i) * Kd + k0 + threadIdx.x] = h;
        Tl[(size_t)(nn + i) * Kd + k0 + threadIdx.x] =
            __float2bfloat16_rn(v - __bfloat162float(h));
    }
}

// ---------------------------------------------------------------------------
// Tensor-core GEMM (128x128 tile, BK=32, 3-stage, 2 CTA/SM).
// Epilogue staged through smem for fully coalesced 128B stores.
// mode 0: fp32 out C[M,N] (+bias)
// mode 1: Q-proj -> split bf16 per-head layout (Oh0/Ol0), N=1024
// mode 2: KV-proj -> K half into Oh0/Ol0, V half into Oh1/Ol1, N=2048
// ---------------------------------------------------------------------------
#define BK      32
#define STAGES  3
#define STAGE_BYTES 32768
#define GEMM_SMEM (1024 + STAGES * STAGE_BYTES)

__global__ __launch_bounds__(256, 2) void gemm_mma(
    const __nv_bfloat16* __restrict__ Ah, const __nv_bfloat16* __restrict__ Al,
    const __nv_bfloat16* __restrict__ Bh, const __nv_bfloat16* __restrict__ Bl,
    const float* __restrict__ bias, float* __restrict__ C,
    __nv_bfloat16* __restrict__ Oh0, __nv_bfloat16* __restrict__ Ol0,
    __nv_bfloat16* __restrict__ Oh1, __nv_bfloat16* __restrict__ Ol1,
    int mode, int N, int K)
{
    extern __shared__ char smraw[];
    const uint32_t raw32  = smem_u32(smraw);
    const uint32_t heap32 = (raw32 + 1023) & ~1023u;
    char* heap = smraw + (heap32 - raw32);

    const int tid  = threadIdx.x;
    const int lane = tid & 31, wid = tid >> 5;
    const int wm0  = (wid & 3) * 32;
    const int wn0  = (wid >> 2) * 64;
    const int m0   = blockIdx.y * 128;
    const int n0   = blockIdx.x * 128;

    const bool isA = tid < 128;
    const int  lrow = isA ? tid : tid - 128;
    const __nv_bfloat16* gh = isA ? Ah + (size_t)(m0 + lrow) * K
                                  : Bh + (size_t)(n0 + lrow) * K;
    const __nv_bfloat16* gl = isA ? Al + (size_t)(m0 + lrow) * K
                                  : Bl + (size_t)(n0 + lrow) * K;
    const uint32_t dstBase = heap32 + (isA ? 0u : 16384u);
    uint32_t dsw[8];
    #pragma unroll
    for (int seg = 0; seg < 4; seg++) {
        dsw[seg]     = SW128((uint32_t)(lrow * 128 + seg * 16));
        dsw[4 + seg] = SW128((uint32_t)(lrow * 128 + 64 + seg * 16));
    }

    float acc[2][8][4];
    #pragma unroll
    for (int mt = 0; mt < 2; mt++)
        #pragma unroll
        for (int nt = 0; nt < 8; nt++)
            #pragma unroll
            for (int r = 0; r < 4; r++) acc[mt][nt][r] = 0.f;

    const uint32_t aRowOff = (uint32_t)((wm0 + (lane & 15)) * 128 + ((lane >> 4) << 4));
    const uint32_t bRowOff = (uint32_t)((wn0 + (lane & 15)) * 128 + ((lane >> 4) << 4));

    const int steps = K / BK;

    #pragma unroll
    for (int s = 0; s < 2; s++) {
        #pragma unroll
        for (int seg = 0; seg < 4; seg++) {
            CP16(dstBase + s * STAGE_BYTES + dsw[seg],     gh + s * BK + seg * 8);
            CP16(dstBase + s * STAGE_BYTES + dsw[4 + seg], gl + s * BK + seg * 8);
        }
        CP_COMMIT();
    }

    for (int i = 0; i < steps; i++) {
        CP_WAIT1();
        __syncthreads();

        if (i + 2 < steps) {
            const int s = (i + 2) % STAGES;
            const int k0 = (i + 2) * BK;
            #pragma unroll
            for (int seg = 0; seg < 4; seg++) {
                CP16(dstBase + s * STAGE_BYTES + dsw[seg],     gh + k0 + seg * 8);
                CP16(dstBase + s * STAGE_BYTES + dsw[4 + seg], gl + k0 + seg * 8);
            }
        }
        CP_COMMIT();

        const uint32_t aB = heap32 + (i % STAGES) * STAGE_BYTES;
        const uint32_t bB = aB + 16384;

        #pragma unroll
        for (int kh = 0; kh < 2; kh++) {
            uint32_t afh[2][4], afl[2][4];
            #pragma unroll
            for (int mt = 0; mt < 2; mt++) {
                uint32_t off = aRowOff + (uint32_t)(mt * 16 * 128 + kh * 32);
                LDSM_X4(afh[mt], aB + SW128(off));
                LDSM_X4(afl[mt], aB + SW128(off + 64));
            }
            #pragma unroll
            for (int p = 0; p < 4; p++) {
                uint32_t off = bRowOff + (uint32_t)(p * 16 * 128 + kh * 32);
                uint32_t b4h[4], b4l[4];
                LDSM_X4(b4h, bB + SW128(off));
                LDSM_X4(b4l, bB + SW128(off + 64));
                uint32_t bh0[2] = {b4h[0], b4h[2]}, bh1[2] = {b4h[1], b4h[3]};
                uint32_t bl0[2] = {b4l[0], b4l[2]}, bl1[2] = {b4l[1], b4l[3]};
                #pragma unroll
                for (int mt = 0; mt < 2; mt++) {
                    MMA16816(acc[mt][2 * p],     afh[mt], bh0);
                    MMA16816(acc[mt][2 * p],     afh[mt], bl0);
                    MMA16816(acc[mt][2 * p],     afl[mt], bh0);
                    MMA16816(acc[mt][2 * p + 1], afh[mt], bh1);
                    MMA16816(acc[mt][2 * p + 1], afh[mt], bl1);
                    MMA16816(acc[mt][2 * p + 1], afl[mt], bh1);
                }
            }
        }
    }

    // ---- epilogue: stage tile in smem (pitch 136, conflict-free), then
    //      write 128B-contiguous row-halves to global ----
    __syncthreads();
    const int erow = lane >> 2, ecol = (lane & 3) * 2;

    if (mode == 0) {
        float* sf = (float*)heap;            // 128 x 136 fp32 = 69632 B
        #pragma unroll
        for (int nt = 0; nt < 8; nt++) {
            int c = wn0 + nt * 8 + ecol;
            float2 bv = *(const float2*)&bias[n0 + c];
            #pragma unroll
            for (int mt = 0; mt < 2; mt++) {
                int r = wm0 + mt * 16 + erow;
                float2 v0, v1;
                v0.x = acc[mt][nt][0] + bv.x;  v0.y = acc[mt][nt][1] + bv.y;
                v1.x = acc[mt][nt][2] + bv.x;  v1.y = acc[mt][nt][3] + bv.y;
                *(float2*)&sf[r * 136 + c]       = v0;
                *(float2*)&sf[(r + 8) * 136 + c] = v1;
            }
        }
        __syncthreads();
        const int sr = tid >> 1, half = tid & 1;
        const float* src = &sf[sr * 136 + half * 64];
        float* dst = &C[(size_t)(m0 + sr) * N + n0 + half * 64];
        #pragma unroll
        for (int j = 0; j < 16; j++)
            *(float4*)&dst[j * 4] = *(const float4*)&src[j * 4];
    } else {
        __nv_bfloat16* sh = (__nv_bfloat16*)heap;        // 128 x 136 bf16
        __nv_bfloat16* sl = sh + 128 * 136;              // 2 x 34816 B
        #pragma unroll
        for (int nt = 0; nt < 8; nt++) {
            int c = wn0 + nt * 8 + ecol;
            float2 bv = *(const float2*)&bias[n0 + c];
            #pragma unroll
            for (int mt = 0; mt < 2; mt++) {
                int r = wm0 + mt * 16 + erow;
                uint32_t hi, lo;
                split2(acc[mt][nt][0] + bv.x, acc[mt][nt][1] + bv.y, hi, lo);
                *(uint32_t*)&sh[r * 136 + c] = hi;
                *(uint32_t*)&sl[r * 136 + c] = lo;
                split2(acc[mt][nt][2] + bv.x, acc[mt][nt][3] + bv.y, hi, lo);
                *(uint32_t*)&sh[(r + 8) * 136 + c] = hi;
                *(uint32_t*)&sl[(r + 8) * 136 + c] = lo;
            }
        }
        __syncthreads();
        const int sr = tid >> 1, half = tid & 1;
        const int n = n0 + half * 64;
        __nv_bfloat16 *oh, *ol;
        int h;
        if (mode == 1 || n < 1024) { h = (n & 1023) >> 6; oh = Oh0; ol = Ol0; }
        else                        { h = (n - 1024) >> 6; oh = Oh1; ol = Ol1; }
        const int row = m0 + sr, b = row >> 11, s = row & 2047;
        const size_t didx = (((size_t)(b * 16 + h)) * 2048 + s) * 64;
        const __nv_bfloat16* srch = &sh[sr * 136 + half * 64];
        const __nv_bfloat16* srcl = &sl[sr * 136 + half * 64];
        #pragma unroll
        for (int j = 0; j < 8; j++) {          // FIX: 8 x uint4 = 64 bf16 (was 4)
            *(uint4*)&oh[didx + j * 8] = *(const uint4*)&srch[j * 8];
            *(uint4*)&ol[didx + j * 8] = *(const uint4*)&srcl[j * 8];
        }
    }
}

// ---------------------------------------------------------------------------
// Tensor-core flash attention (R5-validated core; split bf16 epilogue)
// ---------------------------------------------------------------------------
#define ATTN_SMEM (98304 + 1024)

__global__ __launch_bounds__(256, 2) void attn_tc(
    const __nv_bfloat16* __restrict__ Qh2, const __nv_bfloat16* __restrict__ Ql2,
    const __nv_bfloat16* __restrict__ Kh2, const __nv_bfloat16* __restrict__ Kl2,
    const __nv_bfloat16* __restrict__ Vh2, const __nv_bfloat16* __restrict__ Vl2,
    __nv_bfloat16* __restrict__ ch, __nv_bfloat16* __restrict__ cl)
{
    extern __shared__ char smraw[];
    const uint32_t raw32  = smem_u32(smraw);
    const uint32_t heap32 = (raw32 + 1023) & ~1023u;

    const int tid  = threadIdx.x;
    const int lane = tid & 31, wid = tid >> 5;
    const int q0 = blockIdx.x * 128;
    const int h  = blockIdx.y, b = blockIdx.z;
    const int bh = b * H_ + h;
    const size_t headQ = (size_t)bh * SQ_ * 64;
    const size_t headK = (size_t)bh * SK_ * 64;

    const uint32_t QH = heap32, QL = heap32 + 16384;
    #define STG(s) (heap32 + 32768u + (uint32_t)(s) * 32768u)

    {
        const int arr = tid >> 7, r = tid & 127;
        const __nv_bfloat16* src = (arr ? Ql2 : Qh2) + headQ + (size_t)(q0 + r) * 64;
        const uint32_t dst = heap32 + (uint32_t)arr * 16384u;
        #pragma unroll
        for (int seg = 0; seg < 8; seg++)
            CP16(dst + SW128((uint32_t)(r * 128 + seg * 16)), src + seg * 8);
    }
    const int larr = tid >> 6, lrow = tid & 63;
    const __nv_bfloat16* lsrc0 =
        (larr == 0 ? Kh2 : larr == 1 ? Kl2 : larr == 2 ? Vh2 : Vl2) + headK + (size_t)lrow * 64;
    uint32_t lsw[8];
    #pragma unroll
    for (int seg = 0; seg < 8; seg++)
        lsw[seg] = (uint32_t)larr * 8192u + SW128((uint32_t)(lrow * 128 + seg * 16));

    #pragma unroll
    for (int seg = 0; seg < 8; seg++)
        CP16(STG(0) + lsw[seg], lsrc0 + seg * 8);
    CP_COMMIT();

    float oacc[8][4];
    #pragma unroll
    for (int nt = 0; nt < 8; nt++)
        #pragma unroll
        for (int r = 0; r < 4; r++) oacc[nt][r] = 0.f;
    float mrow[2] = {-1e30f, -1e30f}, lrowsum[2] = {0.f, 0.f};

    const float c2 = SCALE_ * 1.44269504088896340736f;
    const int wm = wid * 16;
    const uint32_t aOff = (uint32_t)((wm + (lane & 15)) * 128 + ((lane >> 4) << 4));
    const uint32_t kOff = (uint32_t)((lane & 15) * 128 + ((lane >> 4) << 4));
    const uint32_t vOff = (uint32_t)((lane & 15) * 128 + ((lane >> 4) << 4));

    const int iters = SK_ / 64;
    for (int i = 0; i < iters; i++) {
        __syncthreads();
        if (i + 1 < iters) {
            const __nv_bfloat16* src = lsrc0 + (size_t)(i + 1) * 64 * 64;
            const uint32_t stg = STG((i + 1) & 1);
            #pragma unroll
            for (int seg = 0; seg < 8; seg++)
                CP16(stg + lsw[seg], src + seg * 8);
        }
        CP_COMMIT();
        CP_WAIT1();
        __syncthreads();

        const uint32_t KH = STG(i & 1), KL = KH + 8192, VH = KH + 16384, VL = KH + 24576;

        float sacc[8][4];
        #pragma unroll
        for (int nt = 0; nt < 8; nt++)
            #pragma unroll
            for (int r = 0; r < 4; r++) sacc[nt][r] = 0.f;

        #pragma unroll
        for (int kc = 0; kc < 4; kc++) {
            uint32_t afh[4], afl[4];
            LDSM_X4(afh, QH + SW128(aOff + kc * 32));
            LDSM_X4(afl, QL + SW128(aOff + kc * 32));
            #pragma unroll
            for (int ntp = 0; ntp < 4; ntp++) {
                uint32_t b4h[4], b4l[4];
                uint32_t off = kOff + (uint32_t)(ntp * 2048 + kc * 32);
                LDSM_X4(b4h, KH + SW128(off));
                LDSM_X4(b4l, KL + SW128(off));
                uint32_t bh0[2] = {b4h[0], b4h[2]}, bh1[2] = {b4h[1], b4h[3]};
                uint32_t bl0[2] = {b4l[0], b4l[2]}, bl1[2] = {b4l[1], b4l[3]};
                MMA16816(sacc[2 * ntp],     afh, bh0);
                MMA16816(sacc[2 * ntp],     afh, bl0);
                MMA16816(sacc[2 * ntp],     afl, bh0);
                MMA16816(sacc[2 * ntp + 1], afh, bh1);
                MMA16816(sacc[2 * ntp + 1], afh, bl1);
                MMA16816(sacc[2 * ntp + 1], afl, bh1);
            }
        }

        float fac[2];
        #pragma unroll
        for (int j = 0; j < 2; j++) {
            float tmax = -1e30f;
            #pragma unroll
            for (int nt = 0; nt < 8; nt++)
                tmax = fmaxf(tmax, fmaxf(sacc[nt][2 * j], sacc[nt][2 * j + 1]));
            tmax = fmaxf(tmax, __shfl_xor_sync(0xffffffffu, tmax, 1));
            tmax = fmaxf(tmax, __shfl_xor_sync(0xffffffffu, tmax, 2));
            float mn = fmaxf(mrow[j], tmax);
            fac[j] = exp2f((mrow[j] - mn) * c2);
            mrow[j] = mn;
            float tsum = 0.f;
            #pragma unroll
            for (int nt = 0; nt < 8; nt++) {
                float p0 = exp2f((sacc[nt][2 * j]     - mn) * c2);
                float p1 = exp2f((sacc[nt][2 * j + 1] - mn) * c2);
                sacc[nt][2 * j] = p0; sacc[nt][2 * j + 1] = p1;
                tsum += p0 + p1;
            }
            tsum += __shfl_xor_sync(0xffffffffu, tsum, 1);
            tsum += __shfl_xor_sync(0xffffffffu, tsum, 2);
            lrowsum[j] = lrowsum[j] * fac[j] + tsum;
            #pragma unroll
            for (int nt = 0; nt < 8; nt++) {
                oacc[nt][2 * j]     *= fac[j];
                oacc[nt][2 * j + 1] *= fac[j];
            }
        }

        #pragma unroll
        for (int kc = 0; kc < 4; kc++) {
            uint32_t ah[4], al[4];
            split2(sacc[2 * kc][0],     sacc[2 * kc][1],     ah[0], al[0]);
            split2(sacc[2 * kc][2],     sacc[2 * kc][3],     ah[1], al[1]);
            split2(sacc[2 * kc + 1][0], sacc[2 * kc + 1][1], ah[2], al[2]);
            split2(sacc[2 * kc + 1][2], sacc[2 * kc + 1][3], ah[3], al[3]);
            #pragma unroll
            for (int ntp = 0; ntp < 4; ntp++) {
                uint32_t v4h[4], v4l[4];
                uint32_t off = vOff + (uint32_t)(kc * 2048 + ntp * 32);
                LDSM_X4_T(v4h, VH + SW128(off));
                LDSM_X4_T(v4l, VL + SW128(off));
                uint32_t bh0[2] = {v4h[0], v4h[1]}, bh1[2] = {v4h[2], v4h[3]};
                uint32_t bl0[2] = {v4l[0], v4l[1]}, bl1[2] = {v4l[2], v4l[3]};
                MMA16816(oacc[2 * ntp],     ah, bh0);
                MMA16816(oacc[2 * ntp],     ah, bl0);
                MMA16816(oacc[2 * ntp],     al, bh0);
                MMA16816(oacc[2 * ntp + 1], ah, bh1);
                MMA16816(oacc[2 * ntp + 1], ah, bl1);
                MMA16816(oacc[2 * ntp + 1], al, bh1);
            }
        }
    }

    // normalize + split-store ctx (hi/lo bf16) in [b, sq, D] layout
    const float inv0 = 1.f / lrowsum[0], inv1 = 1.f / lrowsum[1];
    const int r0 = q0 + wm + (lane >> 2);
    const int col0 = h * 64 + (lane & 3) * 2;
    #pragma unroll
    for (int nt = 0; nt < 8; nt++) {
        int col = col0 + nt * 8;
        size_t i0 = ((size_t)(b * SQ_ + r0))     * D_ + col;
        size_t i1 = ((size_t)(b * SQ_ + r0 + 8)) * D_ + col;
        uint32_t hi, lo;
        split2(oacc[nt][0] * inv0, oacc[nt][1] * inv0, hi, lo);
        *(uint32_t*)&ch[i0] = hi;  *(uint32_t*)&cl[i0] = lo;
        split2(oacc[nt][2] * inv1, oacc[nt][3] * inv1, hi, lo);
        *(uint32_t*)&ch[i1] = hi;  *(uint32_t*)&cl[i1] = lo;
    }
}

// ---------------------------------------------------------------------------
extern "C" void kernel_launch(void* const* d_in, const int* in_sizes, int n_in,
                              void* d_out, int out_size)
{
    const float* query     = (const float*)d_in[0];
    const float* key_value = (const float*)d_in[1];
    const float* Wq        = (const float*)d_in[2];
    const float* bq        = (const float*)d_in[3];
    const float* Wkv       = (const float*)d_in[4];
    const float* bkv       = (const float*)d_in[5];
    const float* Wo        = (const float*)d_in[6];
    const float* bo        = (const float*)d_in[7];
    float* out = (float*)d_out;

    __nv_bfloat16 *qh, *ql, *kh, *kl, *ch, *cl;
    __nv_bfloat16 *WqTh, *WqTl, *WkvTh, *WkvTl, *WoTh, *WoTl;
    __nv_bfloat16 *Qh2, *Ql2, *Kh2, *Kl2, *Vh2, *Vl2;
    cudaGetSymbolAddress((void**)&qh,   g_qh);   cudaGetSymbolAddress((void**)&ql, g_ql);
    cudaGetSymbolAddress((void**)&kh,   g_kh);   cudaGetSymbolAddress((void**)&kl, g_kl);
    cudaGetSymbolAddress((void**)&ch,   g_ch);   cudaGetSymbolAddress((void**)&cl, g_cl);
    cudaGetSymbolAddress((void**)&WqTh, g_WqTh); cudaGetSymbolAddress((void**)&WqTl, g_WqTl);
    cudaGetSymbolAddress((void**)&WkvTh,g_WkvTh);cudaGetSymbolAddress((void**)&WkvTl,g_WkvTl);
    cudaGetSymbolAddress((void**)&WoTh, g_WoTh); cudaGetSymbolAddress((void**)&WoTl, g_WoTl);
    cudaGetSymbolAddress((void**)&Qh2,  g_Qh2);  cudaGetSymbolAddress((void**)&Ql2, g_Ql2);
    cudaGetSymbolAddress((void**)&Kh2,  g_Kh2);  cudaGetSymbolAddress((void**)&Kl2, g_Kl2);
    cudaGetSymbolAddress((void**)&Vh2,  g_Vh2);  cudaGetSymbolAddress((void**)&Vl2, g_Vl2);

    cudaFuncSetAttribute(gemm_mma, cudaFuncAttributeMaxDynamicSharedMemorySize, GEMM_SMEM);
    cudaFuncSetAttribute(attn_tc,  cudaFuncAttributeMaxDynamicSharedMemorySize, ATTN_SMEM);

    // Launch order chosen so launch idx 4 (ncu capture point) = gemm_mma(Q).
    prep_wT<<<dim3(D_ / 32,     D_ / 32), dim3(32, 8)>>>(Wq,  WqTh,  WqTl,  D_, D_);
    prep_wT<<<dim3(2 * D_ / 32, D_ / 32), dim3(32, 8)>>>(Wkv, WkvTh, WkvTl, D_, 2 * D_);
    prep_act<<<2048, 256>>>(query,     qh, ql, M_TOT * D_ / 4);
    prep_act<<<2048, 256>>>(key_value, kh, kl, M_TOT * D_ / 4);

    // Q projection -> per-head split (mode 1)   [launch idx 4]
    gemm_mma<<<dim3(D_ / 128, M_TOT / 128), 256, GEMM_SMEM>>>(
        qh, ql, WqTh, WqTl, bq, nullptr, Qh2, Ql2, nullptr, nullptr, 1, D_, D_);

    // Wo prep (only needed by O projection)
    prep_wT<<<dim3(D_ / 32, D_ / 32), dim3(32, 8)>>>(Wo, WoTh, WoTl, D_, D_);

    // KV projection -> per-head split K + V (mode 2)
    gemm_mma<<<dim3(2 * D_ / 128, M_TOT / 128), 256, GEMM_SMEM>>>(
        kh, kl, WkvTh, WkvTl, bkv, nullptr, Kh2, Kl2, Vh2, Vl2, 2, 2 * D_, D_);

    // Attention -> split ctx (ch/cl)
    attn_tc<<<dim3(SQ_ / 128, H_, B_), 256, ATTN_SMEM>>>(
        Qh2, Ql2, Kh2, Kl2, Vh2, Vl2, ch, cl);

    // O projection -> fp32 out (mode 0)
    gemm_mma<<<dim3(D_ / 128, M_TOT / 128), 256, GEMM_SMEM>>>(
        ch, cl, WoTh, WoTl, bo, out, nullptr, nullptr, nullptr, nullptr, 0, D_, D_);
}